// round 15
// baseline (speedup 1.0000x reference)
#include <cuda_runtime.h>
#include <cuda_bf16.h>
#include <cstdint>

// ---------------- problem constants ----------------
#define NBR 4
#define BB  8
#define CC  8
#define NAA 128
#define T0  200
#define T1  100
#define DD  200
#define VV  8192
#define NQ  8
#define ROWS (BB*NAA)        // 1024

#define N_Y1  (NBR*BB*CC*NAA*T0)
#define N_Y3  (NBR*BB*CC*NAA*T1)
#define N_FT  (NBR*ROWS*DD)
#define N_IDX (NBR*NQ*ROWS)

#define KPAD 224             // padded K (bf16): 200 data + 24 zeros, 14 x 16
#define KC   32              // K chunk (two k16 mma steps per chunk)
#define NCH  (KPAD/KC)       // 7
#define NT   128             // codes per col tile
#define NTILES (VV/NT)       // 64
#define RERANK_DELTA 0.25f   // wide exact-rerank window (>10 sigma of coarse noise)

// smem slab: 128 rows x 32 bf16 (64B) padded to 80B per row
#define SLAB_B 10240         // 128*80
#define BUF_B  (2*SLAB_B)    // a_hi, b_hi = 20480
#define NSTAGE 3
#define DSMEM  (NSTAGE*BUF_B)   // 61440

// ---------------- scratch ----------------
// Arrays touched by cp.async / vector loads are force-aligned to 16B —
// cp.async.16 faults on misaligned global addresses; base alignment of
// __device__ arrays is otherwise layout-dependent (R8 failure mode).
__device__ float g_y1[N_Y1];
__device__ float g_y3[N_Y3];
__device__ float g_part1[2*NBR*BB*4*NAA];    // [which][br,b,group][na]
__device__ float g_part2[2*NBR*BB*4*NAA];
__device__ float g_feats[N_FT];
__device__ float g_res[N_FT];
__device__ float g_quant[N_FT];
__device__ float g_cnorm[NBR*NQ*VV];
__device__ int   g_idx[N_IDX];
__device__ __align__(16) uint32_t g_cbh[(size_t)NBR*NQ*VV*(KPAD/2)];  // bf16 hi image; pads stay 0
__device__ __align__(16) __nv_bfloat16 g_res_hi[NBR*ROWS*KPAD];       // zero-init pads stay zero
__device__ __align__(16) unsigned long long g_cand[(size_t)NBR*ROWS*NTILES*2];

// ---------------- helpers ----------------
__device__ __forceinline__ float gelu_exact(float v) {
    return 0.5f * v * (1.0f + erff(v * 0.70710678118654752440f));
}
__device__ __forceinline__ unsigned fkey(float f) {
    unsigned u = __float_as_uint(f);
    return (u & 0x80000000u) ? ~u : (u | 0x80000000u);
}
__device__ __forceinline__ float fkey_inv(unsigned k) {
    unsigned u = (k & 0x80000000u) ? (k & 0x7FFFFFFFu) : ~k;
    return __uint_as_float(u);
}
__device__ __forceinline__ uint32_t smem_u32(const void* p) {
    uint32_t a;
    asm("{ .reg .u64 t; cvta.to.shared.u64 t, %1; cvt.u32.u64 %0, t; }" : "=r"(a) : "l"(p));
    return a;
}
#define CP_ASYNC16(dst, src) \
    asm volatile("cp.async.cg.shared.global [%0], [%1], 16;" :: "r"(dst), "l"(src))
#define CP_COMMIT() asm volatile("cp.async.commit_group;" ::: "memory")
#define CP_WAIT(n)  asm volatile("cp.async.wait_group %0;" :: "n"(n) : "memory")

__device__ __forceinline__ void mma_bf16(float* c,
    uint32_t a0, uint32_t a1, uint32_t a2, uint32_t a3, uint32_t b0, uint32_t b1)
{
    asm volatile("mma.sync.aligned.m16n8k16.row.col.f32.bf16.bf16.f32 "
        "{%0,%1,%2,%3}, {%4,%5,%6,%7}, {%8,%9}, {%0,%1,%2,%3};"
        : "+f"(c[0]), "+f"(c[1]), "+f"(c[2]), "+f"(c[3])
        : "r"(a0), "r"(a1), "r"(a2), "r"(a3), "r"(b0), "r"(b1));
}
__device__ __forceinline__ void ldmatrix_x4(uint32_t& r0, uint32_t& r1,
                                            uint32_t& r2, uint32_t& r3, uint32_t addr)
{
    asm volatile("ldmatrix.sync.aligned.m8n8.x4.shared.b16 {%0,%1,%2,%3}, [%4];"
        : "=r"(r0), "=r"(r1), "=r"(r2), "=r"(r3) : "r"(addr));
}

// ---------------- conv1: fused group-stat partials; K-specialized ----------------
#define CONV1_BODY(KV) { \
    const int base0 = 16 + t - ((KV - 1) >> 1); \
    _Pragma("unroll") \
    for (int c = 0; c < CC; ++c) { \
        float acc = b1v[c]; \
        const float* wr = ws + c * KV; \
        _Pragma("unroll") \
        for (int k = 0; k < KV; ++k) acc += xs[base0 + k] * wr[k]; \
        y[c] = acc; \
    } }

__global__ void conv1_kernel(const float* __restrict__ x,
                             const float* __restrict__ w0, const float* __restrict__ w1,
                             const float* __restrict__ w2, const float* __restrict__ w3,
                             const float* __restrict__ b1,
                             int k0, int k1, int k2, int k3)
{
    int na = blockIdx.x, b = blockIdx.y, br = blockIdx.z;
    int tid = threadIdx.x, lane = tid & 31, wid = tid >> 5;

    const float* w; int K;
    if (br == 0)      { w = w0; K = k0; }
    else if (br == 1) { w = w1; K = k1; }
    else if (br == 2) { w = w2; K = k2; }
    else              { w = w3; K = k3; }

    __shared__ float xs[T0 + 32];
    __shared__ float ws[CC * 24];
    __shared__ float wred[8][8];

    if (tid < T0) xs[16 + tid] = x[(size_t)(b * NAA + na) * T0 + tid];
    else if (tid < T0 + 16) xs[tid - T0] = 0.f;
    else if (tid < T0 + 32) xs[tid] = 0.f;
    if (tid < CC * K) ws[tid] = w[tid];
    __syncthreads();

    bool act = tid < T0;
    int t = act ? tid : 0;
    const float* b1v = b1 + br * CC;
    float y[CC];
    if (K == 21)      CONV1_BODY(21)
    else if (K == 15) CONV1_BODY(15)
    else if (K == 9)  CONV1_BODY(9)
    else if (K == 5)  CONV1_BODY(5)
    else {
        int pad = (K - 1) >> 1;
        int base0 = 16 + t - pad;
        for (int c = 0; c < CC; ++c) {
            float acc = b1v[c];
            const float* wr = ws + c * K;
            for (int k = 0; k < K; ++k) acc += xs[base0 + k] * wr[k];
            y[c] = acc;
        }
    }
    if (act) {
        size_t outBase = (((size_t)(br * BB + b) * CC) * NAA + na) * T0 + t;
        #pragma unroll
        for (int c = 0; c < CC; ++c) g_y1[outBase + (size_t)c * NAA * T0] = y[c];
    }

    float pv[8];
    #pragma unroll
    for (int gq = 0; gq < 4; ++gq) {
        float a0 = act ? y[2 * gq] : 0.f;
        float a1 = act ? y[2 * gq + 1] : 0.f;
        pv[gq]     = a0 + a1;
        pv[4 + gq] = a0 * a0 + a1 * a1;
    }
    #pragma unroll
    for (int v = 0; v < 8; ++v)
        #pragma unroll
        for (int o = 16; o; o >>= 1) pv[v] += __shfl_xor_sync(0xffffffffu, pv[v], o);
    if (lane == 0) {
        #pragma unroll
        for (int v = 0; v < 8; ++v) wred[wid][v] = pv[v];
    }
    __syncthreads();
    if (tid < 8) {
        float s = 0.f;
        #pragma unroll
        for (int ww = 0; ww < 8; ++ww) s += wred[ww][tid];
        int gq = tid & 3, which = tid >> 2;
        g_part1[((which * (NBR * BB) + br * BB + b) * 4 + gq) * NAA + na] = s;
    }
}

// ---------------- conv2: GN1(from partials)+gelu+pool2 + conv + stat2 partials ----------------
#define CONV2_TAPS(KV) { \
    const int base0 = 8 + t - ((KV - 1) >> 1); \
    _Pragma("unroll") \
    for (int it = 0; it < 4; ++it) { \
        int co = 2 * it + hi; \
        float acc = b2[br * CC + co]; \
        _Pragma("unroll") \
        for (int ci = 0; ci < CC; ++ci) { \
            const float* wr = ws + (co * CC + ci) * KV; \
            const float* yr = &yin[ci][base0]; \
            _Pragma("unroll") \
            for (int k = 0; k < KV; ++k) acc += yr[k] * wr[k]; \
        } \
        accv[it] = acc; \
    } }

__global__ void conv2_kernel(const float* __restrict__ w0, const float* __restrict__ w1,
                             const float* __restrict__ w2, const float* __restrict__ w3,
                             const float* __restrict__ b2,
                             const float* __restrict__ g1, const float* __restrict__ be1,
                             int k0, int k1, int k2, int k3)
{
    int na = blockIdx.x, b = blockIdx.y, br = blockIdx.z;
    int tid = threadIdx.x, lane = tid & 31, wid = tid >> 5;

    const float* w; int K;
    if (br == 0)      { w = w0; K = k0; }
    else if (br == 1) { w = w1; K = k1; }
    else if (br == 2) { w = w2; K = k2; }
    else              { w = w3; K = k3; }

    __shared__ float yin[CC][T1 + 16];
    __shared__ float ws[CC * CC * 12];
    __shared__ float2 st[4];
    __shared__ float wred[8][8];

    if (wid < 4) {
        float s = 0.f, q = 0.f;
        int b0 = ((br * BB + b) * 4 + wid) * NAA;
        #pragma unroll
        for (int j = 0; j < 4; ++j) {
            s += g_part1[b0 + lane + 32 * j];
            q += g_part1[NBR * BB * 4 * NAA + b0 + lane + 32 * j];
        }
        #pragma unroll
        for (int o = 16; o; o >>= 1) {
            s += __shfl_xor_sync(0xffffffffu, s, o);
            q += __shfl_xor_sync(0xffffffffu, q, o);
        }
        if (lane == 0) {
            float n = 2.0f * NAA * T0;
            float m = s / n;
            float var = q / n - m * m;
            st[wid] = make_float2(m, rsqrtf(var + 1e-5f));
        }
    }
    for (int i = tid; i < CC * CC * K; i += 256) ws[i] = w[i];

    int hi = (tid >= 100) ? 1 : 0;
    int t  = tid - 100 * hi;
    bool act = (tid < 200);
    if (tid >= 200) {
        for (int i = tid - 200; i < 128; i += 56) {
            int ch = i >> 4, j = i & 15;
            yin[ch][(j < 8) ? j : (100 + j)] = 0.f;
        }
    }
    __syncthreads();

    #pragma unroll
    for (int it = 0; it < 4; ++it) {
        int ci = 2 * it + hi;
        if (act) {
            float m = st[ci >> 1].x, r = st[ci >> 1].y;
            float sc = r * g1[br * CC + ci];
            float sh = be1[br * CC + ci] - m * sc;
            size_t base = (((size_t)(br * BB + b) * CC + ci) * NAA + na) * T0 + 2 * t;
            float a0 = gelu_exact(g_y1[base]     * sc + sh);
            float a1 = gelu_exact(g_y1[base + 1] * sc + sh);
            yin[ci][8 + t] = 0.5f * (a0 + a1);
        }
    }
    __syncthreads();

    float accv[4] = {0.f, 0.f, 0.f, 0.f};
    if (act) {
        if (K == 9)      CONV2_TAPS(9)
        else if (K == 7) CONV2_TAPS(7)
        else if (K == 5) CONV2_TAPS(5)
        else if (K == 3) CONV2_TAPS(3)
        else {
            int base0 = 8 + t - ((K - 1) >> 1);
            for (int it = 0; it < 4; ++it) {
                int co = 2 * it + hi;
                float acc = b2[br * CC + co];
                for (int ci = 0; ci < CC; ++ci) {
                    const float* wr = ws + (co * CC + ci) * K;
                    const float* yr = &yin[ci][base0];
                    for (int k = 0; k < K; ++k) acc += yr[k] * wr[k];
                }
                accv[it] = acc;
            }
        }
        #pragma unroll
        for (int it = 0; it < 4; ++it) {
            int co = 2 * it + hi;
            g_y3[(((size_t)(br * BB + b) * CC + co) * NAA + na) * T1 + t] = accv[it];
        }
    }

    float pv[8];
    #pragma unroll
    for (int it = 0; it < 4; ++it) {
        float a = act ? accv[it] : 0.f;
        pv[it] = a;
        pv[4 + it] = a * a;
    }
    #pragma unroll
    for (int v = 0; v < 8; ++v)
        #pragma unroll
        for (int o = 16; o; o >>= 1) pv[v] += __shfl_xor_sync(0xffffffffu, pv[v], o);
    if (lane == 0) {
        #pragma unroll
        for (int v = 0; v < 8; ++v) wred[wid][v] = pv[v];
    }
    __syncthreads();
    if (tid < 8) {
        float s = 0.f;
        #pragma unroll
        for (int ww = 0; ww < 8; ++ww) s += wred[ww][tid];
        int gq = tid & 3, which = tid >> 2;
        g_part2[((which * (NBR * BB) + br * BB + b) * 4 + gq) * NAA + na] = s;
    }
}

// ---------------- feats (GN2+gelu+pool4+transpose) fused with codebook pack+cnorm ----------------
__global__ void feats_pack_kernel(const float* __restrict__ cbAll,
                                  const float* __restrict__ g2, const float* __restrict__ be2)
{
    int bx = blockIdx.x, b = blockIdx.y, br = blockIdx.z;
    int tid = threadIdx.x, lane = tid & 31, wid = tid >> 5;

    if (bx >= NAA) {
        // ---- pack part: warp per code (bf16 hi only) + exact fp32 norms ----
        int px = bx - NAA;
        int cid = (px * BB + b) * 8 + wid;
        size_t gcode = (size_t)br * (NQ * VV) + cid;
        const float* src = cbAll + gcode * DD;
        uint32_t* dh = g_cbh + gcode * (KPAD / 2);
        float s = 0.f;
        #pragma unroll
        for (int p = lane; p < DD / 2; p += 32) {
            float v0 = src[2 * p], v1 = src[2 * p + 1];
            s += v0 * v0 + v1 * v1;
            __nv_bfloat16 h0 = __float2bfloat16(v0), h1 = __float2bfloat16(v1);
            dh[p] = ((uint32_t)__bfloat16_as_ushort(h1) << 16) | __bfloat16_as_ushort(h0);
        }
        #pragma unroll
        for (int o = 16; o; o >>= 1) s += __shfl_xor_sync(0xffffffffu, s, o);
        if (lane == 0) g_cnorm[gcode] = s;
        return;
    }

    // ---- feats part ----
    int na = bx;
    __shared__ float2 st[4];
    if (wid < 4) {
        float s = 0.f, q = 0.f;
        int b0 = ((br * BB + b) * 4 + wid) * NAA;
        #pragma unroll
        for (int j = 0; j < 4; ++j) {
            s += g_part2[b0 + lane + 32 * j];
            q += g_part2[NBR * BB * 4 * NAA + b0 + lane + 32 * j];
        }
        #pragma unroll
        for (int o = 16; o; o >>= 1) {
            s += __shfl_xor_sync(0xffffffffu, s, o);
            q += __shfl_xor_sync(0xffffffffu, q, o);
        }
        if (lane == 0) {
            float n = 2.0f * NAA * T1;
            float m = s / n;
            float var = q / n - m * m;
            st[wid] = make_float2(m, rsqrtf(var + 1e-5f));
        }
    }
    __syncthreads();

    int d = tid;
    if (d >= DD) return;
    int t = d >> 3;
    int c = d & 7;
    float m = st[c >> 1].x, r = st[c >> 1].y;
    float sc = r * g2[br * CC + c];
    float sh = be2[br * CC + c] - m * sc;

    size_t base = (((size_t)(br * BB + b) * CC + c) * NAA + na) * T1 + 4 * t;
    float v = 0.25f * (gelu_exact(g_y3[base]     * sc + sh) +
                       gelu_exact(g_y3[base + 1] * sc + sh) +
                       gelu_exact(g_y3[base + 2] * sc + sh) +
                       gelu_exact(g_y3[base + 3] * sc + sh));
    int row = b * NAA + na;
    size_t fi = ((size_t)br * ROWS + row) * DD + d;
    g_feats[fi] = v;
    g_res[fi]   = v;
    g_quant[fi] = 0.0f;
    g_res_hi[((size_t)((br << 10) + row)) * KPAD + d] = __float2bfloat16(v);
}

// ---------------- mma.sync distance GEMM + per-tile top-2 epilogue ----------------
// grid (8 rowtiles, 4 br, 64 coltiles), block 256 (8 warps, 2x4), warp tile 64x32.
// Single-term coarse distance hi_a·hi_b; exact fp32 rerank recovers indices.
// ldmatrix fragments; 7 chunks of K=32 (two k16 steps per barrier), 3-stage cp.async.
__global__ void __launch_bounds__(256, 2) gemm_step_kernel(int step)
{
    extern __shared__ char dsm[];
    __shared__ float cns[NT];

    int tid = threadIdx.x;
    int lane = tid & 31;
    int wid = tid >> 5;
    int warpM = wid & 1;
    int warpN = wid >> 1;
    int g  = lane >> 2;
    int tig = lane & 3;

    int rowBase = blockIdx.x * 128;
    int br = blockIdx.y;
    int ct = blockIdx.z;
    int brq = br * NQ + step;

    const __nv_bfloat16* aH = g_res_hi + (size_t)((br << 10) + rowBase) * KPAD;
    const __nv_bfloat16* bH = (const __nv_bfloat16*)g_cbh + ((size_t)brq * VV + (size_t)ct * NT) * KPAD;

    if (tid < NT) cns[tid] = g_cnorm[(size_t)brq * VV + ct * NT + tid];

    uint32_t dbase = smem_u32(dsm);
    // ldmatrix lane-offsets (80B pitch; 8-row phase words 20r mod 32 -> conflict-free)
    uint32_t aoff = (uint32_t)(warpM * 64 + (lane & 15)) * 80u + (uint32_t)(lane >> 4) * 16u;
    uint32_t boff = (uint32_t)SLAB_B
                  + (uint32_t)(warpN * 32 + ((lane >> 4) << 3) + (lane & 7)) * 80u
                  + (uint32_t)((lane >> 3) & 1) * 16u;

    // two 16B cp.async per thread per slab (64B per row per chunk); slabs: aH, bH
    auto load_chunk = [&](int buf, int k0) {
        char* base = dsm + buf * BUF_B;
        int row = tid >> 1, s0 = tid & 1;
        uint32_t d0 = smem_u32(base + row * 80);
        const __nv_bfloat16* ga = aH + (size_t)row * KPAD + k0;
        const __nv_bfloat16* gb = bH + (size_t)row * KPAD + k0;
        CP_ASYNC16(d0 + (uint32_t)s0 * 16u,           ga + s0 * 8);
        CP_ASYNC16(d0 + (uint32_t)(s0 + 2) * 16u,     ga + (s0 + 2) * 8);
        CP_ASYNC16(d0 + SLAB_B + (uint32_t)s0 * 16u,       gb + s0 * 8);
        CP_ASYNC16(d0 + SLAB_B + (uint32_t)(s0 + 2) * 16u, gb + (s0 + 2) * 8);
        CP_COMMIT();
    };

    float acc[4][4][4];
    #pragma unroll
    for (int t = 0; t < 4; ++t)
        #pragma unroll
        for (int n = 0; n < 4; ++n)
            #pragma unroll
            for (int e = 0; e < 4; ++e) acc[t][n][e] = 0.f;

    load_chunk(0, 0);
    load_chunk(1, KC);

    #pragma unroll 1
    for (int c = 0; c < NCH; ++c) {
        if (c + 2 < NCH) CP_WAIT(1);   // chunk c done; c+1 may be in flight
        else             CP_WAIT(0);   // drain at the tail
        __syncthreads();               // chunk c visible; buf (c+2)%3 free
        if (c + 2 < NCH) load_chunk((c + 2) % NSTAGE, (c + 2) * KC);

        uint32_t bufb = dbase + (uint32_t)(c % NSTAGE) * BUF_B;

        #pragma unroll
        for (int k16 = 0; k16 < 2; ++k16) {
            uint32_t kadd = (uint32_t)k16 * 32u;
            uint32_t bh[4][2];
            #pragma unroll
            for (int p = 0; p < 2; ++p) {
                uint32_t r0, r1, r2, r3;
                ldmatrix_x4(r0, r1, r2, r3, bufb + boff + kadd + (uint32_t)p * (16u * 80u));
                bh[2 * p][0] = r0;     bh[2 * p][1] = r1;
                bh[2 * p + 1][0] = r2; bh[2 * p + 1][1] = r3;
            }
            #pragma unroll
            for (int t = 0; t < 4; ++t) {
                uint32_t a0, a1, a2, a3;
                ldmatrix_x4(a0, a1, a2, a3, bufb + aoff + kadd + (uint32_t)t * (16u * 80u));
                #pragma unroll
                for (int n = 0; n < 4; ++n)
                    mma_bf16(acc[t][n], a0, a1, a2, a3, bh[n][0], bh[n][1]);
            }
        }
    }
    __syncthreads();   // all compute done before epilogue reuses smem

    // ---- epilogue: per-row top-2 across the 128-code tile ----
    unsigned long long* red = (unsigned long long*)dsm;   // [128][4][2]

    #pragma unroll
    for (int t = 0; t < 4; ++t) {
        #pragma unroll
        for (int rs = 0; rs < 2; ++rs) {
            unsigned long long k1 = ~0ull, k2 = ~0ull;
            #pragma unroll
            for (int n = 0; n < 4; ++n) {
                int lc = warpN * 32 + n * 8 + tig * 2;
                int gc = ct * NT + lc;
                float d0 = cns[lc]     - 2.0f * acc[t][n][rs * 2 + 0];
                float d1 = cns[lc + 1] - 2.0f * acc[t][n][rs * 2 + 1];
                unsigned long long ka = ((unsigned long long)fkey(d0) << 32) | (unsigned)gc;
                unsigned long long kb = ((unsigned long long)fkey(d1) << 32) | (unsigned)(gc + 1);
                if (ka < k1) { k2 = k1; k1 = ka; } else if (ka < k2) k2 = ka;
                if (kb < k1) { k2 = k1; k1 = kb; } else if (kb < k2) k2 = kb;
            }
            #pragma unroll
            for (int off = 1; off <= 2; off <<= 1) {
                unsigned long long o1 = __shfl_xor_sync(0xffffffffu, k1, off);
                unsigned long long o2 = __shfl_xor_sync(0xffffffffu, k2, off);
                unsigned long long n1 = (k1 < o1) ? k1 : o1;
                unsigned long long mx = (k1 < o1) ? o1 : k1;
                unsigned long long mn2 = (k2 < o2) ? k2 : o2;
                k1 = n1;
                k2 = (mx < mn2) ? mx : mn2;
            }
            if (tig == 0) {
                int row = warpM * 64 + t * 16 + rs * 8 + g;
                red[(row * 4 + warpN) * 2 + 0] = k1;
                red[(row * 4 + warpN) * 2 + 1] = k2;
            }
        }
    }
    __syncthreads();

    if (tid < 128) {
        unsigned long long b1 = ~0ull, b2 = ~0ull;
        #pragma unroll
        for (int w = 0; w < 4; ++w)
            #pragma unroll
            for (int e = 0; e < 2; ++e) {
                unsigned long long k = red[(tid * 4 + w) * 2 + e];
                if (k < b1) { b2 = b1; b1 = k; } else if (k < b2) b2 = k;
            }
        size_t ci = ((size_t)((br << 10) + rowBase + tid)) * (NTILES * 2) + ct * 2;
        g_cand[ci] = b1;
        g_cand[ci + 1] = b2;
    }
}

// ---------------- rerank (exact fp32 within delta) + update ----------------
__global__ void rerank_update_kernel(const float* __restrict__ cbAll, int step)
{
    int row = blockIdx.x, br = blockIdx.y;
    int tid = threadIdx.x, lane = tid & 31, w = tid >> 5;

    __shared__ float rsm[DD];
    __shared__ unsigned long long keys[NTILES * 2];
    __shared__ unsigned long long sBest, sExact;

    size_t rbase = ((size_t)br * ROWS + row) * DD;
    if (tid < DD) rsm[tid] = g_res[rbase + tid];
    if (tid < NTILES * 2) keys[tid] = g_cand[((size_t)((br << 10) + row)) * (NTILES * 2) + tid];
    if (tid == 0) { sBest = ~0ull; sExact = ~0ull; }
    __syncthreads();
    if (tid < NTILES * 2) atomicMin(&sBest, keys[tid]);
    __syncthreads();

    float bestA = fkey_inv((unsigned)(sBest >> 32));
    const float* cbq = cbAll + (size_t)(br * NQ + step) * VV * DD;
    const float* cnq = g_cnorm + (size_t)(br * NQ + step) * VV;

    for (int c = w; c < NTILES * 2; c += 8) {
        unsigned long long k = keys[c];
        float da = fkey_inv((unsigned)(k >> 32));
        if (da <= bestA + RERANK_DELTA) {
            int code = (int)(k & 0xFFFFFFFFull);
            const float* cr = cbq + (size_t)code * DD;
            float dot = 0.f;
            for (int d = lane; d < DD; d += 32) dot += rsm[d] * cr[d];
            #pragma unroll
            for (int o = 16; o; o >>= 1) dot += __shfl_xor_sync(0xffffffffu, dot, o);
            if (lane == 0) {
                float de = cnq[code] - 2.0f * dot;
                unsigned long long ke = ((unsigned long long)fkey(de) << 32) | (unsigned)code;
                atomicMin(&sExact, ke);
            }
        }
    }
    __syncthreads();

    int idx = (int)(sExact & 0xFFFFFFFFull);
    const float* q = cbq + (size_t)idx * DD;
    if (tid < DD) {
        float qv = q[tid];
        float r = rsm[tid] - qv;
        g_res[rbase + tid] = r;
        g_quant[rbase + tid] += qv;
        g_res_hi[((size_t)((br << 10) + row)) * KPAD + tid] = __float2bfloat16(r);
    }
    if (tid == 0) g_idx[(br * NQ + step) * ROWS + row] = idx;
}

// ---------------- final output ----------------
__global__ void final_kernel(float* __restrict__ out, int n)
{
    int i = blockIdx.x * 256 + threadIdx.x;
    if (i >= n) return;
    if (i < N_FT) {
        float f = g_feats[i];
        out[i] = f + (g_quant[i] - f);
    } else {
        int j = i - N_FT;
        out[i] = (j < N_IDX) ? (float)g_idx[j] : 0.0f;
    }
}

// ---------------- launch ----------------
extern "C" void kernel_launch(void* const* d_in, const int* in_sizes, int n_in,
                              void* d_out, int out_size)
{
    const float* x   = (const float*)d_in[0];
    const float* w11 = (const float*)d_in[1];
    const float* w12 = (const float*)d_in[2];
    const float* w13 = (const float*)d_in[3];
    const float* w14 = (const float*)d_in[4];
    const float* b1  = (const float*)d_in[5];
    const float* g1  = (const float*)d_in[6];
    const float* be1 = (const float*)d_in[7];
    const float* w21 = (const float*)d_in[8];
    const float* w22 = (const float*)d_in[9];
    const float* w23 = (const float*)d_in[10];
    const float* w24 = (const float*)d_in[11];
    const float* b2  = (const float*)d_in[12];
    const float* g2  = (const float*)d_in[13];
    const float* be2 = (const float*)d_in[14];
    const float* cb  = (const float*)d_in[15];

    int K1a = in_sizes[1] / CC,  K1b = in_sizes[2] / CC;
    int K1c = in_sizes[3] / CC,  K1d = in_sizes[4] / CC;
    int K2a = in_sizes[8] / (CC * CC),  K2b = in_sizes[9] / (CC * CC);
    int K2c = in_sizes[10] / (CC * CC), K2d = in_sizes[11] / (CC * CC);

    cudaFuncSetAttribute(gemm_step_kernel, cudaFuncAttributeMaxDynamicSharedMemorySize, DSMEM);

    conv1_kernel<<<dim3(NAA, BB, NBR), 256>>>(x, w11, w12, w13, w14, b1, K1a, K1b, K1c, K1d);
    conv2_kernel<<<dim3(NAA, BB, NBR), 256>>>(w21, w22, w23, w24, b2, g1, be1, K2a, K2b, K2c, K2d);
    feats_pack_kernel<<<dim3(NAA + 1024, BB, NBR), 256>>>(cb, g2, be2);

    for (int s = 0; s < NQ; ++s) {
        gemm_step_kernel<<<dim3(ROWS / 128, NBR, NTILES), 256, DSMEM>>>(s);
        rerank_update_kernel<<<dim3(ROWS, NBR), 256>>>(cb, s);
    }

    final_kernel<<<(out_size + 255) / 256, 256>>>((float*)d_out, out_size);
}

// round 17
// speedup vs baseline: 1.1153x; 1.1153x over previous
#include <cuda_runtime.h>
#include <cuda_bf16.h>
#include <cstdint>

// ---------------- problem constants ----------------
#define NBR 4
#define BB  8
#define CC  8
#define NAA 128
#define T0  200
#define T1  100
#define DD  200
#define VV  8192
#define NQ  8
#define ROWS (BB*NAA)        // 1024

#define N_Y1  (NBR*BB*CC*NAA*T0)
#define N_Y3  (NBR*BB*CC*NAA*T1)
#define N_FT  (NBR*ROWS*DD)
#define N_IDX (NBR*NQ*ROWS)

#define KPAD 208             // padded K (bf16): 200 data + 8 zeros, 13 x 16
#define KC   16              // K chunk (one k16 per chunk)
#define NCH  (KPAD/KC)       // 13
#define NT   128             // codes per col tile
#define NTILES (VV/NT)       // 64
#define RERANK_DELTA 0.25f   // wide exact-rerank window (>10 sigma of coarse noise)

// smem slab: 128 rows x 16 bf16 (32B) padded to 48B per row
#define SLAB_B 6144          // 128*48
#define BUF_B  (2*SLAB_B)    // a_hi, b_hi = 12288
#define NSTAGE 3
#define DSMEM  (NSTAGE*BUF_B)   // 36864

// ---------------- scratch ----------------
// Arrays touched by cp.async / vector loads are force-aligned to 16B —
// cp.async.16 faults on misaligned global addresses; base alignment of
// __device__ arrays is otherwise layout-dependent (R8 failure mode).
__device__ float g_y1[N_Y1];
__device__ float g_y3[N_Y3];
__device__ float g_part1[2*NBR*BB*4*NAA];    // [which][br,b,group][na]
__device__ float g_part2[2*NBR*BB*4*NAA];
__device__ float g_feats[N_FT];
__device__ float g_res[N_FT];
__device__ float g_quant[N_FT];
__device__ float g_cnorm[NBR*NQ*VV];
__device__ int   g_idx[N_IDX];
__device__ __align__(16) uint32_t g_cbh[(size_t)NBR*NQ*VV*(KPAD/2)];  // bf16 hi image; pads stay 0
__device__ __align__(16) __nv_bfloat16 g_res_hi[NBR*ROWS*KPAD];       // zero-init pads stay zero
__device__ __align__(16) unsigned long long g_cand[(size_t)NBR*ROWS*NTILES*2];

// ---------------- helpers ----------------
__device__ __forceinline__ float gelu_exact(float v) {
    return 0.5f * v * (1.0f + erff(v * 0.70710678118654752440f));
}
__device__ __forceinline__ unsigned fkey(float f) {
    unsigned u = __float_as_uint(f);
    return (u & 0x80000000u) ? ~u : (u | 0x80000000u);
}
__device__ __forceinline__ float fkey_inv(unsigned k) {
    unsigned u = (k & 0x80000000u) ? (k & 0x7FFFFFFFu) : ~k;
    return __uint_as_float(u);
}
__device__ __forceinline__ uint32_t smem_u32(const void* p) {
    uint32_t a;
    asm("{ .reg .u64 t; cvta.to.shared.u64 t, %1; cvt.u32.u64 %0, t; }" : "=r"(a) : "l"(p));
    return a;
}
#define CP_ASYNC16(dst, src) \
    asm volatile("cp.async.cg.shared.global [%0], [%1], 16;" :: "r"(dst), "l"(src))
#define CP_COMMIT() asm volatile("cp.async.commit_group;" ::: "memory")
#define CP_WAIT(n)  asm volatile("cp.async.wait_group %0;" :: "n"(n) : "memory")

__device__ __forceinline__ void mma_bf16(float* c,
    uint32_t a0, uint32_t a1, uint32_t a2, uint32_t a3, uint32_t b0, uint32_t b1)
{
    asm volatile("mma.sync.aligned.m16n8k16.row.col.f32.bf16.bf16.f32 "
        "{%0,%1,%2,%3}, {%4,%5,%6,%7}, {%8,%9}, {%0,%1,%2,%3};"
        : "+f"(c[0]), "+f"(c[1]), "+f"(c[2]), "+f"(c[3])
        : "r"(a0), "r"(a1), "r"(a2), "r"(a3), "r"(b0), "r"(b1));
}
__device__ __forceinline__ void ldmatrix_x4(uint32_t& r0, uint32_t& r1,
                                            uint32_t& r2, uint32_t& r3, uint32_t addr)
{
    asm volatile("ldmatrix.sync.aligned.m8n8.x4.shared.b16 {%0,%1,%2,%3}, [%4];"
        : "=r"(r0), "=r"(r1), "=r"(r2), "=r"(r3) : "r"(addr));
}

// ---------------- conv1: fused group-stat partials; K-specialized ----------------
#define CONV1_BODY(KV) { \
    const int base0 = 16 + t - ((KV - 1) >> 1); \
    _Pragma("unroll") \
    for (int c = 0; c < CC; ++c) { \
        float acc = b1v[c]; \
        const float* wr = ws + c * KV; \
        _Pragma("unroll") \
        for (int k = 0; k < KV; ++k) acc += xs[base0 + k] * wr[k]; \
        y[c] = acc; \
    } }

__global__ void conv1_kernel(const float* __restrict__ x,
                             const float* __restrict__ w0, const float* __restrict__ w1,
                             const float* __restrict__ w2, const float* __restrict__ w3,
                             const float* __restrict__ b1,
                             int k0, int k1, int k2, int k3)
{
    int na = blockIdx.x, b = blockIdx.y, br = blockIdx.z;
    int tid = threadIdx.x, lane = tid & 31, wid = tid >> 5;

    const float* w; int K;
    if (br == 0)      { w = w0; K = k0; }
    else if (br == 1) { w = w1; K = k1; }
    else if (br == 2) { w = w2; K = k2; }
    else              { w = w3; K = k3; }

    __shared__ float xs[T0 + 32];
    __shared__ float ws[CC * 24];
    __shared__ float wred[8][8];

    if (tid < T0) xs[16 + tid] = x[(size_t)(b * NAA + na) * T0 + tid];
    else if (tid < T0 + 16) xs[tid - T0] = 0.f;
    else if (tid < T0 + 32) xs[tid] = 0.f;
    if (tid < CC * K) ws[tid] = w[tid];
    __syncthreads();

    bool act = tid < T0;
    int t = act ? tid : 0;
    const float* b1v = b1 + br * CC;
    float y[CC];
    if (K == 21)      CONV1_BODY(21)
    else if (K == 15) CONV1_BODY(15)
    else if (K == 9)  CONV1_BODY(9)
    else if (K == 5)  CONV1_BODY(5)
    else {
        int pad = (K - 1) >> 1;
        int base0 = 16 + t - pad;
        for (int c = 0; c < CC; ++c) {
            float acc = b1v[c];
            const float* wr = ws + c * K;
            for (int k = 0; k < K; ++k) acc += xs[base0 + k] * wr[k];
            y[c] = acc;
        }
    }
    if (act) {
        size_t outBase = (((size_t)(br * BB + b) * CC) * NAA + na) * T0 + t;
        #pragma unroll
        for (int c = 0; c < CC; ++c) g_y1[outBase + (size_t)c * NAA * T0] = y[c];
    }

    float pv[8];
    #pragma unroll
    for (int gq = 0; gq < 4; ++gq) {
        float a0 = act ? y[2 * gq] : 0.f;
        float a1 = act ? y[2 * gq + 1] : 0.f;
        pv[gq]     = a0 + a1;
        pv[4 + gq] = a0 * a0 + a1 * a1;
    }
    #pragma unroll
    for (int v = 0; v < 8; ++v)
        #pragma unroll
        for (int o = 16; o; o >>= 1) pv[v] += __shfl_xor_sync(0xffffffffu, pv[v], o);
    if (lane == 0) {
        #pragma unroll
        for (int v = 0; v < 8; ++v) wred[wid][v] = pv[v];
    }
    __syncthreads();
    if (tid < 8) {
        float s = 0.f;
        #pragma unroll
        for (int ww = 0; ww < 8; ++ww) s += wred[ww][tid];
        int gq = tid & 3, which = tid >> 2;
        g_part1[((which * (NBR * BB) + br * BB + b) * 4 + gq) * NAA + na] = s;
    }
}

// ---------------- conv2: GN1(from partials)+gelu+pool2 + conv + stat2 partials ----------------
#define CONV2_TAPS(KV) { \
    const int base0 = 8 + t - ((KV - 1) >> 1); \
    _Pragma("unroll") \
    for (int it = 0; it < 4; ++it) { \
        int co = 2 * it + hi; \
        float acc = b2[br * CC + co]; \
        _Pragma("unroll") \
        for (int ci = 0; ci < CC; ++ci) { \
            const float* wr = ws + (co * CC + ci) * KV; \
            const float* yr = &yin[ci][base0]; \
            _Pragma("unroll") \
            for (int k = 0; k < KV; ++k) acc += yr[k] * wr[k]; \
        } \
        accv[it] = acc; \
    } }

__global__ void conv2_kernel(const float* __restrict__ w0, const float* __restrict__ w1,
                             const float* __restrict__ w2, const float* __restrict__ w3,
                             const float* __restrict__ b2,
                             const float* __restrict__ g1, const float* __restrict__ be1,
                             int k0, int k1, int k2, int k3)
{
    int na = blockIdx.x, b = blockIdx.y, br = blockIdx.z;
    int tid = threadIdx.x, lane = tid & 31, wid = tid >> 5;

    const float* w; int K;
    if (br == 0)      { w = w0; K = k0; }
    else if (br == 1) { w = w1; K = k1; }
    else if (br == 2) { w = w2; K = k2; }
    else              { w = w3; K = k3; }

    __shared__ float yin[CC][T1 + 16];
    __shared__ float ws[CC * CC * 12];
    __shared__ float2 st[4];
    __shared__ float wred[8][8];

    if (wid < 4) {
        float s = 0.f, q = 0.f;
        int b0 = ((br * BB + b) * 4 + wid) * NAA;
        #pragma unroll
        for (int j = 0; j < 4; ++j) {
            s += g_part1[b0 + lane + 32 * j];
            q += g_part1[NBR * BB * 4 * NAA + b0 + lane + 32 * j];
        }
        #pragma unroll
        for (int o = 16; o; o >>= 1) {
            s += __shfl_xor_sync(0xffffffffu, s, o);
            q += __shfl_xor_sync(0xffffffffu, q, o);
        }
        if (lane == 0) {
            float n = 2.0f * NAA * T0;
            float m = s / n;
            float var = q / n - m * m;
            st[wid] = make_float2(m, rsqrtf(var + 1e-5f));
        }
    }
    for (int i = tid; i < CC * CC * K; i += 256) ws[i] = w[i];

    int hi = (tid >= 100) ? 1 : 0;
    int t  = tid - 100 * hi;
    bool act = (tid < 200);
    if (tid >= 200) {
        for (int i = tid - 200; i < 128; i += 56) {
            int ch = i >> 4, j = i & 15;
            yin[ch][(j < 8) ? j : (100 + j)] = 0.f;
        }
    }
    __syncthreads();

    #pragma unroll
    for (int it = 0; it < 4; ++it) {
        int ci = 2 * it + hi;
        if (act) {
            float m = st[ci >> 1].x, r = st[ci >> 1].y;
            float sc = r * g1[br * CC + ci];
            float sh = be1[br * CC + ci] - m * sc;
            size_t base = (((size_t)(br * BB + b) * CC + ci) * NAA + na) * T0 + 2 * t;
            float a0 = gelu_exact(g_y1[base]     * sc + sh);
            float a1 = gelu_exact(g_y1[base + 1] * sc + sh);
            yin[ci][8 + t] = 0.5f * (a0 + a1);
        }
    }
    __syncthreads();

    float accv[4] = {0.f, 0.f, 0.f, 0.f};
    if (act) {
        if (K == 9)      CONV2_TAPS(9)
        else if (K == 7) CONV2_TAPS(7)
        else if (K == 5) CONV2_TAPS(5)
        else if (K == 3) CONV2_TAPS(3)
        else {
            int base0 = 8 + t - ((K - 1) >> 1);
            for (int it = 0; it < 4; ++it) {
                int co = 2 * it + hi;
                float acc = b2[br * CC + co];
                for (int ci = 0; ci < CC; ++ci) {
                    const float* wr = ws + (co * CC + ci) * K;
                    const float* yr = &yin[ci][base0];
                    for (int k = 0; k < K; ++k) acc += yr[k] * wr[k];
                }
                accv[it] = acc;
            }
        }
        #pragma unroll
        for (int it = 0; it < 4; ++it) {
            int co = 2 * it + hi;
            g_y3[(((size_t)(br * BB + b) * CC + co) * NAA + na) * T1 + t] = accv[it];
        }
    }

    float pv[8];
    #pragma unroll
    for (int it = 0; it < 4; ++it) {
        float a = act ? accv[it] : 0.f;
        pv[it] = a;
        pv[4 + it] = a * a;
    }
    #pragma unroll
    for (int v = 0; v < 8; ++v)
        #pragma unroll
        for (int o = 16; o; o >>= 1) pv[v] += __shfl_xor_sync(0xffffffffu, pv[v], o);
    if (lane == 0) {
        #pragma unroll
        for (int v = 0; v < 8; ++v) wred[wid][v] = pv[v];
    }
    __syncthreads();
    if (tid < 8) {
        float s = 0.f;
        #pragma unroll
        for (int ww = 0; ww < 8; ++ww) s += wred[ww][tid];
        int gq = tid & 3, which = tid >> 2;
        g_part2[((which * (NBR * BB) + br * BB + b) * 4 + gq) * NAA + na] = s;
    }
}

// ---------------- feats (GN2+gelu+pool4+transpose) fused with codebook pack+cnorm ----------------
__global__ void feats_pack_kernel(const float* __restrict__ cbAll,
                                  const float* __restrict__ g2, const float* __restrict__ be2)
{
    int bx = blockIdx.x, b = blockIdx.y, br = blockIdx.z;
    int tid = threadIdx.x, lane = tid & 31, wid = tid >> 5;

    if (bx >= NAA) {
        // ---- pack part: warp per code (bf16 hi only) + exact fp32 norms ----
        int px = bx - NAA;
        int cid = (px * BB + b) * 8 + wid;
        size_t gcode = (size_t)br * (NQ * VV) + cid;
        const float* src = cbAll + gcode * DD;
        uint32_t* dh = g_cbh + gcode * (KPAD / 2);
        float s = 0.f;
        #pragma unroll
        for (int p = lane; p < DD / 2; p += 32) {
            float v0 = src[2 * p], v1 = src[2 * p + 1];
            s += v0 * v0 + v1 * v1;
            __nv_bfloat16 h0 = __float2bfloat16(v0), h1 = __float2bfloat16(v1);
            dh[p] = ((uint32_t)__bfloat16_as_ushort(h1) << 16) | __bfloat16_as_ushort(h0);
        }
        #pragma unroll
        for (int o = 16; o; o >>= 1) s += __shfl_xor_sync(0xffffffffu, s, o);
        if (lane == 0) g_cnorm[gcode] = s;
        return;
    }

    // ---- feats part ----
    int na = bx;
    __shared__ float2 st[4];
    if (wid < 4) {
        float s = 0.f, q = 0.f;
        int b0 = ((br * BB + b) * 4 + wid) * NAA;
        #pragma unroll
        for (int j = 0; j < 4; ++j) {
            s += g_part2[b0 + lane + 32 * j];
            q += g_part2[NBR * BB * 4 * NAA + b0 + lane + 32 * j];
        }
        #pragma unroll
        for (int o = 16; o; o >>= 1) {
            s += __shfl_xor_sync(0xffffffffu, s, o);
            q += __shfl_xor_sync(0xffffffffu, q, o);
        }
        if (lane == 0) {
            float n = 2.0f * NAA * T1;
            float m = s / n;
            float var = q / n - m * m;
            st[wid] = make_float2(m, rsqrtf(var + 1e-5f));
        }
    }
    __syncthreads();

    int d = tid;
    if (d >= DD) return;
    int t = d >> 3;
    int c = d & 7;
    float m = st[c >> 1].x, r = st[c >> 1].y;
    float sc = r * g2[br * CC + c];
    float sh = be2[br * CC + c] - m * sc;

    size_t base = (((size_t)(br * BB + b) * CC + c) * NAA + na) * T1 + 4 * t;
    float v = 0.25f * (gelu_exact(g_y3[base]     * sc + sh) +
                       gelu_exact(g_y3[base + 1] * sc + sh) +
                       gelu_exact(g_y3[base + 2] * sc + sh) +
                       gelu_exact(g_y3[base + 3] * sc + sh));
    int row = b * NAA + na;
    size_t fi = ((size_t)br * ROWS + row) * DD + d;
    g_feats[fi] = v;
    g_res[fi]   = v;
    g_quant[fi] = 0.0f;
    g_res_hi[((size_t)((br << 10) + row)) * KPAD + d] = __float2bfloat16(v);
}

// ---------------- mma.sync distance GEMM + per-tile top-2 epilogue ----------------
// grid (8 rowtiles, 4 br, 64 coltiles), block 256 (8 warps, 2x4), warp tile 64x32.
// Single-term coarse distance hi_a·hi_b; exact fp32 rerank recovers indices.
// ldmatrix fragments, 3-stage cp.async. Epilogue tracks top-2 as raw float+idx
// (no per-candidate fkey/u64 packing) — coarse ties resolved by exact rerank.
__global__ void __launch_bounds__(256, 2) gemm_step_kernel(int step)
{
    extern __shared__ char dsm[];
    __shared__ float cns[NT];

    int tid = threadIdx.x;
    int lane = tid & 31;
    int wid = tid >> 5;
    int warpM = wid & 1;
    int warpN = wid >> 1;
    int g  = lane >> 2;
    int tig = lane & 3;

    int rowBase = blockIdx.x * 128;
    int br = blockIdx.y;
    int ct = blockIdx.z;
    int brq = br * NQ + step;

    const __nv_bfloat16* aH = g_res_hi + (size_t)((br << 10) + rowBase) * KPAD;
    const __nv_bfloat16* bH = (const __nv_bfloat16*)g_cbh + ((size_t)brq * VV + (size_t)ct * NT) * KPAD;

    if (tid < NT) cns[tid] = g_cnorm[(size_t)brq * VV + ct * NT + tid];

    uint32_t dbase = smem_u32(dsm);
    uint32_t aoff = (uint32_t)(warpM * 64 + (lane & 15)) * 48u + (uint32_t)(lane >> 4) * 16u;
    uint32_t boff = (uint32_t)SLAB_B
                  + (uint32_t)(warpN * 32 + ((lane >> 4) << 3) + (lane & 7)) * 48u
                  + (uint32_t)((lane >> 3) & 1) * 16u;

    auto load_chunk = [&](int buf, int k0) {
        char* base = dsm + buf * BUF_B;
        int row = tid >> 1, seg = tid & 1;
        uint32_t d0 = smem_u32(base + row * 48 + seg * 16);
        CP_ASYNC16(d0,          aH + (size_t)row * KPAD + k0 + seg * 8);
        CP_ASYNC16(d0 + SLAB_B, bH + (size_t)row * KPAD + k0 + seg * 8);
        CP_COMMIT();
    };

    float acc[4][4][4];
    #pragma unroll
    for (int t = 0; t < 4; ++t)
        #pragma unroll
        for (int n = 0; n < 4; ++n)
            #pragma unroll
            for (int e = 0; e < 4; ++e) acc[t][n][e] = 0.f;

    load_chunk(0, 0);
    load_chunk(1, KC);

    #pragma unroll 1
    for (int c = 0; c < NCH; ++c) {
        if (c + 2 < NCH) CP_WAIT(1);
        else             CP_WAIT(0);
        __syncthreads();
        if (c + 2 < NCH) load_chunk((c + 2) % NSTAGE, (c + 2) * KC);

        uint32_t bufb = dbase + (uint32_t)(c % NSTAGE) * BUF_B;

        uint32_t bh[4][2];
        #pragma unroll
        for (int p = 0; p < 2; ++p) {
            uint32_t r0, r1, r2, r3;
            ldmatrix_x4(r0, r1, r2, r3, bufb + boff + (uint32_t)p * (16u * 48u));
            bh[2 * p][0] = r0;     bh[2 * p][1] = r1;
            bh[2 * p + 1][0] = r2; bh[2 * p + 1][1] = r3;
        }
        #pragma unroll
        for (int t = 0; t < 4; ++t) {
            uint32_t a0, a1, a2, a3;
            ldmatrix_x4(a0, a1, a2, a3, bufb + aoff + (uint32_t)t * (16u * 48u));
            #pragma unroll
            for (int n = 0; n < 4; ++n)
                mma_bf16(acc[t][n], a0, a1, a2, a3, bh[n][0], bh[n][1]);
        }
    }
    __syncthreads();   // all compute done before epilogue reuses smem

    // ---- epilogue: per-row top-2 across the 128-code tile (float+idx tracking) ----
    unsigned long long* red = (unsigned long long*)dsm;   // [128][4][2]

    #pragma unroll
    for (int t = 0; t < 4; ++t) {
        #pragma unroll
        for (int rs = 0; rs < 2; ++rs) {
            float bd1 = 3.4e38f, bd2 = 3.4e38f;
            int   bi1 = 0,       bi2 = 0;
            #pragma unroll
            for (int n = 0; n < 4; ++n) {
                int lc = warpN * 32 + n * 8 + tig * 2;
                int gc = ct * NT + lc;
                float d0 = cns[lc]     - 2.0f * acc[t][n][rs * 2 + 0];
                float d1 = cns[lc + 1] - 2.0f * acc[t][n][rs * 2 + 1];
                if (d0 < bd1)      { bd2 = bd1; bi2 = bi1; bd1 = d0; bi1 = gc; }
                else if (d0 < bd2) { bd2 = d0; bi2 = gc; }
                if (d1 < bd1)      { bd2 = bd1; bi2 = bi1; bd1 = d1; bi1 = gc + 1; }
                else if (d1 < bd2) { bd2 = d1; bi2 = gc + 1; }
            }
            // merge top-2 lists across the 4 quad lanes sharing this row
            #pragma unroll
            for (int off = 1; off <= 2; off <<= 1) {
                float od1 = __shfl_xor_sync(0xffffffffu, bd1, off);
                int   oi1 = __shfl_xor_sync(0xffffffffu, bi1, off);
                float od2 = __shfl_xor_sync(0xffffffffu, bd2, off);
                int   oi2 = __shfl_xor_sync(0xffffffffu, bi2, off);
                if (od1 < bd1) {
                    bd2 = (bd1 < od2) ? bd1 : od2;
                    bi2 = (bd1 < od2) ? bi1 : oi2;
                    bd1 = od1; bi1 = oi1;
                } else if (od1 < bd2) {
                    bd2 = od1; bi2 = oi1;
                }
            }
            if (tig == 0) {
                int row = warpM * 64 + t * 16 + rs * 8 + g;
                red[(row * 4 + warpN) * 2 + 0] =
                    ((unsigned long long)fkey(bd1) << 32) | (unsigned)bi1;
                red[(row * 4 + warpN) * 2 + 1] =
                    ((unsigned long long)fkey(bd2) << 32) | (unsigned)bi2;
            }
        }
    }
    __syncthreads();

    if (tid < 128) {
        unsigned long long b1 = ~0ull, b2 = ~0ull;
        #pragma unroll
        for (int w = 0; w < 4; ++w)
            #pragma unroll
            for (int e = 0; e < 2; ++e) {
                unsigned long long k = red[(tid * 4 + w) * 2 + e];
                if (k < b1) { b2 = b1; b1 = k; } else if (k < b2) b2 = k;
            }
        size_t ci = ((size_t)((br << 10) + rowBase + tid)) * (NTILES * 2) + ct * 2;
        g_cand[ci] = b1;
        g_cand[ci + 1] = b2;
    }
}

// ---------------- rerank (exact fp32 within delta) + update ----------------
__global__ void rerank_update_kernel(const float* __restrict__ cbAll, int step)
{
    int row = blockIdx.x, br = blockIdx.y;
    int tid = threadIdx.x, lane = tid & 31, w = tid >> 5;

    __shared__ float rsm[DD];
    __shared__ unsigned long long keys[NTILES * 2];
    __shared__ unsigned long long sBest, sExact;

    size_t rbase = ((size_t)br * ROWS + row) * DD;
    if (tid < DD) rsm[tid] = g_res[rbase + tid];
    if (tid < NTILES * 2) keys[tid] = g_cand[((size_t)((br << 10) + row)) * (NTILES * 2) + tid];
    if (tid == 0) { sBest = ~0ull; sExact = ~0ull; }
    __syncthreads();
    if (tid < NTILES * 2) atomicMin(&sBest, keys[tid]);
    __syncthreads();

    float bestA = fkey_inv((unsigned)(sBest >> 32));
    const float* cbq = cbAll + (size_t)(br * NQ + step) * VV * DD;
    const float* cnq = g_cnorm + (size_t)(br * NQ + step) * VV;

    for (int c = w; c < NTILES * 2; c += 8) {
        unsigned long long k = keys[c];
        float da = fkey_inv((unsigned)(k >> 32));
        if (da <= bestA + RERANK_DELTA) {
            int code = (int)(k & 0xFFFFFFFFull);
            const float* cr = cbq + (size_t)code * DD;
            float dot = 0.f;
            for (int d = lane; d < DD; d += 32) dot += rsm[d] * cr[d];
            #pragma unroll
            for (int o = 16; o; o >>= 1) dot += __shfl_xor_sync(0xffffffffu, dot, o);
            if (lane == 0) {
                float de = cnq[code] - 2.0f * dot;
                unsigned long long ke = ((unsigned long long)fkey(de) << 32) | (unsigned)code;
                atomicMin(&sExact, ke);
            }
        }
    }
    __syncthreads();

    int idx = (int)(sExact & 0xFFFFFFFFull);
    const float* q = cbq + (size_t)idx * DD;
    if (tid < DD) {
        float qv = q[tid];
        float r = rsm[tid] - qv;
        g_res[rbase + tid] = r;
        g_quant[rbase + tid] += qv;
        g_res_hi[((size_t)((br << 10) + row)) * KPAD + tid] = __float2bfloat16(r);
    }
    if (tid == 0) g_idx[(br * NQ + step) * ROWS + row] = idx;
}

// ---------------- final output ----------------
__global__ void final_kernel(float* __restrict__ out, int n)
{
    int i = blockIdx.x * 256 + threadIdx.x;
    if (i >= n) return;
    if (i < N_FT) {
        float f = g_feats[i];
        out[i] = f + (g_quant[i] - f);
    } else {
        int j = i - N_FT;
        out[i] = (j < N_IDX) ? (float)g_idx[j] : 0.0f;
    }
}

// ---------------- launch ----------------
extern "C" void kernel_launch(void* const* d_in, const int* in_sizes, int n_in,
                              void* d_out, int out_size)
{
    const float* x   = (const float*)d_in[0];
    const float* w11 = (const float*)d_in[1];
    const float* w12 = (const float*)d_in[2];
    const float* w13 = (const float*)d_in[3];
    const float* w14 = (const float*)d_in[4];
    const float* b1  = (const float*)d_in[5];
    const float* g1  = (const float*)d_in[6];
    const float* be1 = (const float*)d_in[7];
    const float* w21 = (const float*)d_in[8];
    const float* w22 = (const float*)d_in[9];
    const float* w23 = (const float*)d_in[10];
    const float* w24 = (const float*)d_in[11];
    const float* b2  = (const float*)d_in[12];
    const float* g2  = (const float*)d_in[13];
    const float* be2 = (const float*)d_in[14];
    const float* cb  = (const float*)d_in[15];

    int K1a = in_sizes[1] / CC,  K1b = in_sizes[2] / CC;
    int K1c = in_sizes[3] / CC,  K1d = in_sizes[4] / CC;
    int K2a = in_sizes[8] / (CC * CC),  K2b = in_sizes[9] / (CC * CC);
    int K2c = in_sizes[10] / (CC * CC), K2d = in_sizes[11] / (CC * CC);

    cudaFuncSetAttribute(gemm_step_kernel, cudaFuncAttributeMaxDynamicSharedMemorySize, DSMEM);

    conv1_kernel<<<dim3(NAA, BB, NBR), 256>>>(x, w11, w12, w13, w14, b1, K1a, K1b, K1c, K1d);
    conv2_kernel<<<dim3(NAA, BB, NBR), 256>>>(w21, w22, w23, w24, b2, g1, be1, K2a, K2b, K2c, K2d);
    feats_pack_kernel<<<dim3(NAA + 1024, BB, NBR), 256>>>(cb, g2, be2);

    for (int s = 0; s < NQ; ++s) {
        gemm_step_kernel<<<dim3(ROWS / 128, NBR, NTILES), 256, DSMEM>>>(s);
        rerank_update_kernel<<<dim3(ROWS, NBR), 256>>>(cb, s);
    }

    final_kernel<<<(out_size + 255) / 256, 256>>>((float*)d_out, out_size);
}